// round 1
// baseline (speedup 1.0000x reference)
#include <cuda_runtime.h>
#include <cstdint>

#define Bn   4096
#define Hh   32
#define Ww   32
#define S    1024     // H*W
#define DIN  3072     // H*W*3
#define NOUT 2048     // 2*H*W
#define KITER 20

// ---------------- scratch (device globals; no allocation allowed) ----------
__device__ float d_walls[Bn * S];       // tf32-rounded walls, (B,1024) contiguous
__device__ float d_Wd[S * NOUT];        // tf32-rounded dense weight rows Phi_w[3k,:]
__device__ float d_phi[Bn * NOUT];      // sigmoid output, interleaved (r,p)
__device__ int   d_agent[Bn];
__device__ int   d_goal[Bn];
__device__ float d_aval[Bn];
__device__ float d_gval[Bn];

__device__ __forceinline__ float tf32r(float x) {
    uint32_t u;
    asm("cvt.rna.tf32.f32 %0, %1;" : "=r"(u) : "f"(x));
    return __uint_as_float(u);
}

// ---------------- kernel 0: compact walls + argmax of agent/goal channels --
__global__ void prep_kernel(const float* __restrict__ obs) {
    int b = blockIdx.x;
    const float* row = obs + (size_t)b * DIN;
    __shared__ unsigned long long ka, kg;
    if (threadIdx.x == 0) { ka = 0ull; kg = 0ull; }
    __syncthreads();
    unsigned long long la = 0ull, lg = 0ull;
    for (int s = threadIdx.x; s < S; s += blockDim.x) {
        float w = row[3 * s + 0];
        float a = row[3 * s + 1];
        float g = row[3 * s + 2];
        d_walls[(size_t)b * S + s] = tf32r(w);
        // key: (float bits)<<32 | (inverted index) -> max key = max value, first index
        unsigned long long keya =
            ((unsigned long long)__float_as_uint(a) << 32) | (unsigned)(0xFFFFFFFFu - s);
        unsigned long long keyg =
            ((unsigned long long)__float_as_uint(g) << 32) | (unsigned)(0xFFFFFFFFu - s);
        if (keya > la) la = keya;
        if (keyg > lg) lg = keyg;
    }
    atomicMax(&ka, la);
    atomicMax(&kg, lg);
    __syncthreads();
    if (threadIdx.x == 0) {
        unsigned long long va = ka, vg = kg;
        d_agent[b] = (int)(0xFFFFFFFFu - (unsigned)(va & 0xFFFFFFFFull));
        d_aval[b]  = __uint_as_float((unsigned)(va >> 32));
        d_goal[b]  = (int)(0xFFFFFFFFu - (unsigned)(vg & 0xFFFFFFFFull));
        d_gval[b]  = __uint_as_float((unsigned)(vg >> 32));
    }
}

// ---------------- kernel 1: compact dense weight rows (tf32 rounded) -------
__global__ void wcompact_kernel(const float* __restrict__ Phi_w) {
    int t = blockIdx.x * blockDim.x + threadIdx.x;   // one float4 each
    int k  = t >> 9;          // / (NOUT/4)
    int c4 = t & 511;         // % (NOUT/4)
    const float4* src = (const float4*)Phi_w;
    float4 v = src[(size_t)(3 * k) * (NOUT / 4) + c4];
    v.x = tf32r(v.x); v.y = tf32r(v.y); v.z = tf32r(v.z); v.w = tf32r(v.w);
    ((float4*)d_Wd)[(size_t)k * (NOUT / 4) + c4] = v;
}

// ---------------- kernel 2: tf32 tensor-core GEMM + epilogue ---------------
#define BM 128
#define BN 128
#define BK 16
#define ASTRIDE 20    // padded row stride (floats), conflict-free fragment loads
#define BSTRIDE 136

__device__ __forceinline__ void mma_tf32(float* c, const uint32_t* a, const uint32_t* b) {
    asm volatile(
        "mma.sync.aligned.m16n8k8.row.col.f32.tf32.tf32.f32 "
        "{%0,%1,%2,%3}, {%4,%5,%6,%7}, {%8,%9}, {%0,%1,%2,%3};\n"
        : "+f"(c[0]), "+f"(c[1]), "+f"(c[2]), "+f"(c[3])
        : "r"(a[0]), "r"(a[1]), "r"(a[2]), "r"(a[3]), "r"(b[0]), "r"(b[1]));
}

__global__ __launch_bounds__(256, 2) void gemm_kernel(
    const float* __restrict__ Phi_w, const float* __restrict__ Phi_b)
{
    __shared__ float As[2][BM * ASTRIDE];
    __shared__ float Bs[2][BK * BSTRIDE];

    const int tid  = threadIdx.x;
    const int warp = tid >> 5;
    const int lane = tid & 31;
    const int wm   = warp >> 2;   // 0..1 -> 64 rows each
    const int wn   = warp & 3;    // 0..3 -> 32 cols each
    const int bm   = blockIdx.y * BM;
    const int bn   = blockIdx.x * BN;

    // A tile loads: 128 rows x 4 float4; f = tid, tid+256
    const int a_row0 = tid >> 2, a_c40 = tid & 3;
    const int a_row1 = (tid + 256) >> 2, a_c41 = (tid + 256) & 3;
    // B tile loads: 16 rows x 32 float4
    const int b_row0 = tid >> 5, b_c40 = tid & 31;
    const int b_row1 = (tid + 256) >> 5, b_c41 = (tid + 256) & 31;

    float acc[4][4][4];
    #pragma unroll
    for (int i = 0; i < 4; i++)
        #pragma unroll
        for (int j = 0; j < 4; j++)
            #pragma unroll
            for (int k = 0; k < 4; k++) acc[i][j][k] = 0.f;

    float4 aR0, aR1, bR0, bR1;

    // prologue: load tile 0
    {
        const float4* Ap = (const float4*)d_walls;
        const float4* Bp = (const float4*)d_Wd;
        aR0 = Ap[(size_t)(bm + a_row0) * (S / 4) + a_c40];
        aR1 = Ap[(size_t)(bm + a_row1) * (S / 4) + a_c41];
        bR0 = Bp[(size_t)(b_row0) * (NOUT / 4) + (bn >> 2) + b_c40];
        bR1 = Bp[(size_t)(b_row1) * (NOUT / 4) + (bn >> 2) + b_c41];
        *((float4*)&As[0][a_row0 * ASTRIDE + a_c40 * 4]) = aR0;
        *((float4*)&As[0][a_row1 * ASTRIDE + a_c41 * 4]) = aR1;
        *((float4*)&Bs[0][b_row0 * BSTRIDE + b_c40 * 4]) = bR0;
        *((float4*)&Bs[0][b_row1 * BSTRIDE + b_c41 * 4]) = bR1;
    }
    __syncthreads();

    const int NKT = S / BK;   // 64
    #pragma unroll 1
    for (int kt = 0; kt < NKT; kt++) {
        const int cur = kt & 1, nxt = cur ^ 1;
        if (kt + 1 < NKT) {
            const int ko = (kt + 1) * BK;
            const float4* Ap = (const float4*)d_walls;
            const float4* Bp = (const float4*)d_Wd;
            aR0 = Ap[(size_t)(bm + a_row0) * (S / 4) + (ko >> 2) + a_c40];
            aR1 = Ap[(size_t)(bm + a_row1) * (S / 4) + (ko >> 2) + a_c41];
            bR0 = Bp[(size_t)(ko + b_row0) * (NOUT / 4) + (bn >> 2) + b_c40];
            bR1 = Bp[(size_t)(ko + b_row1) * (NOUT / 4) + (bn >> 2) + b_c41];
        }

        #pragma unroll
        for (int kk = 0; kk < BK; kk += 8) {
            uint32_t afr[4][4];
            uint32_t bfr[4][2];
            #pragma unroll
            for (int mt = 0; mt < 4; mt++) {
                const float* p = &As[cur][(wm * 64 + mt * 16 + (lane >> 2)) * ASTRIDE
                                          + kk + (lane & 3)];
                afr[mt][0] = __float_as_uint(p[0]);
                afr[mt][1] = __float_as_uint(p[8 * ASTRIDE]);
                afr[mt][2] = __float_as_uint(p[4]);
                afr[mt][3] = __float_as_uint(p[8 * ASTRIDE + 4]);
            }
            #pragma unroll
            for (int nt = 0; nt < 4; nt++) {
                const float* q = &Bs[cur][(kk + (lane & 3)) * BSTRIDE
                                          + wn * 32 + nt * 8 + (lane >> 2)];
                bfr[nt][0] = __float_as_uint(q[0]);
                bfr[nt][1] = __float_as_uint(q[4 * BSTRIDE]);
            }
            #pragma unroll
            for (int mt = 0; mt < 4; mt++)
                #pragma unroll
                for (int nt = 0; nt < 4; nt++)
                    mma_tf32(acc[mt][nt], afr[mt], bfr[nt]);
        }

        if (kt + 1 < NKT) {
            *((float4*)&As[nxt][a_row0 * ASTRIDE + a_c40 * 4]) = aR0;
            *((float4*)&As[nxt][a_row1 * ASTRIDE + a_c41 * 4]) = aR1;
            *((float4*)&Bs[nxt][b_row0 * BSTRIDE + b_c40 * 4]) = bR0;
            *((float4*)&Bs[nxt][b_row1 * BSTRIDE + b_c41 * 4]) = bR1;
        }
        __syncthreads();
    }

    // ---- epilogue: + agent/goal row gathers + bias, sigmoid, store (r,p) --
    #pragma unroll
    for (int mt = 0; mt < 4; mt++) {
        #pragma unroll
        for (int rsub = 0; rsub < 2; rsub++) {
            const int gr = bm + wm * 64 + mt * 16 + (lane >> 2) + rsub * 8;
            const int ai = d_agent[gr];
            const int gi = d_goal[gr];
            const float av = d_aval[gr];
            const float gv = d_gval[gr];
            const float* arow = Phi_w + (size_t)(3 * ai + 1) * NOUT;
            const float* grow = Phi_w + (size_t)(3 * gi + 2) * NOUT;
            #pragma unroll
            for (int nt = 0; nt < 4; nt++) {
                const int gn = bn + wn * 32 + nt * 8 + (lane & 3) * 2;
                float x0 = acc[mt][nt][rsub * 2 + 0]
                         + av * arow[gn] + gv * grow[gn] + Phi_b[gn];
                float x1 = acc[mt][nt][rsub * 2 + 1]
                         + av * arow[gn + 1] + gv * grow[gn + 1] + Phi_b[gn + 1];
                float2 o;
                o.x = 1.f / (1.f + __expf(-x0));
                o.y = 1.f / (1.f + __expf(-x1));
                *((float2*)&d_phi[(size_t)gr * NOUT + gn]) = o;
            }
        }
    }
}

// ---------------- kernel 3: value propagation + gather + MLP head ----------
__global__ __launch_bounds__(1024, 2) void vprop_kernel(
    const float* __restrict__ obs,
    const float* __restrict__ L1w, const float* __restrict__ L1b,
    const float* __restrict__ L2w, const float* __restrict__ L2b,
    float* __restrict__ out)
{
    const int b = blockIdx.x;
    const int s = threadIdx.x;        // 0..1023
    const int i = s >> 5, j = s & 31;

    __shared__ float V[2][S];
    __shared__ float sel[36];
    __shared__ float hsh[16];

    float2 rp = ((const float2*)(d_phi + (size_t)b * NOUT))[s];
    const float r = rp.x, p = rp.y;
    float v = r;
    V[0][s] = r;
    __syncthreads();

    int cur = 0;
    #pragma unroll
    for (int it = 0; it < KITER; it++) {
        const float* Vc = V[cur];
        float up = (i > 0)  ? Vc[s - 32] : 0.f;
        float dn = (i < 31) ? Vc[s + 32] : 0.f;
        float lf = (j > 0)  ? Vc[s - 1]  : 0.f;
        float rt = (j < 31) ? Vc[s + 1]  : 0.f;
        float nbr = fmaxf(fmaxf(up, dn), fmaxf(lf, rt));
        v = fmaxf(v, fmaf(p, nbr - r, r));
        V[cur ^ 1][s] = v;
        __syncthreads();
        cur ^= 1;
    }

    // 3x3 gather around agent
    const int ai = d_agent[b];
    const int pi = ai >> 5, pj = ai & 31;
    if (s < 36) {
        const int di = s / 12, dj = (s / 4) % 3, c = s & 3;
        const int ii = pi + di - 1, jj = pj + dj - 1;
        float val = 0.f;
        if (ii >= 0 && ii < 32 && jj >= 0 && jj < 32) {
            const int sp = ii * 32 + jj;
            val = (c < 3) ? obs[(size_t)b * DIN + sp * 3 + c] : V[cur][sp];
        }
        sel[s] = val;
    }
    __syncthreads();
    if (s < 16) {
        float h = L1b[s];
        #pragma unroll
        for (int f = 0; f < 36; f++) h = fmaf(sel[f], L1w[f * 16 + s], h);
        hsh[s] = fmaxf(h, 0.f);
    }
    __syncthreads();
    if (s < 4) {
        float o = L2b[s];
        #pragma unroll
        for (int k = 0; k < 16; k++) o = fmaf(hsh[k], L2w[k * 4 + s], o);
        out[(size_t)b * 4 + s] = o;
    }
}

// ---------------------------------------------------------------------------
extern "C" void kernel_launch(void* const* d_in, const int* in_sizes, int n_in,
                              void* d_out, int out_size) {
    const float* obs   = (const float*)d_in[0];
    const float* Phi_w = (const float*)d_in[1];
    const float* Phi_b = (const float*)d_in[2];
    const float* L1w   = (const float*)d_in[3];
    const float* L1b   = (const float*)d_in[4];
    const float* L2w   = (const float*)d_in[5];
    const float* L2b   = (const float*)d_in[6];
    float* out = (float*)d_out;

    prep_kernel<<<Bn, 256>>>(obs);
    wcompact_kernel<<<(S * NOUT / 4) / 256, 256>>>(Phi_w);
    dim3 g(NOUT / BN, Bn / BM);
    gemm_kernel<<<g, 256>>>(Phi_w, Phi_b);
    vprop_kernel<<<Bn, 1024>>>(obs, L1w, L1b, L2w, L2b, out);
}

// round 2
// speedup vs baseline: 1.3507x; 1.3507x over previous
#include <cuda_runtime.h>
#include <cstdint>

#define Bn   4096
#define Hh   32
#define Ww   32
#define S    1024     // H*W
#define DIN  3072     // H*W*3
#define NOUT 2048     // 2*H*W
#define KITER 20

// ---------------- scratch (device globals; no allocation allowed) ----------
__device__ float d_walls[Bn * S];       // tf32-rounded walls, (B,1024) contiguous
__device__ float d_Wd[S * NOUT];        // tf32-rounded dense weight rows Phi_w[3k,:]
__device__ float d_phi[Bn * NOUT];      // sigmoid output, interleaved (r,p)
__device__ int   d_agent[Bn];
__device__ int   d_goal[Bn];
__device__ float d_aval[Bn];
__device__ float d_gval[Bn];

__device__ __forceinline__ float tf32r(float x) {
    uint32_t u;
    asm("cvt.rna.tf32.f32 %0, %1;" : "=r"(u) : "f"(x));
    return __uint_as_float(u);
}

// ---------------- kernel 0: compact walls + argmax of agent/goal channels --
__global__ void prep_kernel(const float* __restrict__ obs) {
    int b = blockIdx.x;
    const float* row = obs + (size_t)b * DIN;
    __shared__ unsigned long long ka, kg;
    if (threadIdx.x == 0) { ka = 0ull; kg = 0ull; }
    __syncthreads();
    unsigned long long la = 0ull, lg = 0ull;
    for (int s = threadIdx.x; s < S; s += blockDim.x) {
        float w = row[3 * s + 0];
        float a = row[3 * s + 1];
        float g = row[3 * s + 2];
        d_walls[(size_t)b * S + s] = tf32r(w);
        unsigned long long keya =
            ((unsigned long long)__float_as_uint(a) << 32) | (unsigned)(0xFFFFFFFFu - s);
        unsigned long long keyg =
            ((unsigned long long)__float_as_uint(g) << 32) | (unsigned)(0xFFFFFFFFu - s);
        if (keya > la) la = keya;
        if (keyg > lg) lg = keyg;
    }
    atomicMax(&ka, la);
    atomicMax(&kg, lg);
    __syncthreads();
    if (threadIdx.x == 0) {
        unsigned long long va = ka, vg = kg;
        d_agent[b] = (int)(0xFFFFFFFFu - (unsigned)(va & 0xFFFFFFFFull));
        d_aval[b]  = __uint_as_float((unsigned)(va >> 32));
        d_goal[b]  = (int)(0xFFFFFFFFu - (unsigned)(vg & 0xFFFFFFFFull));
        d_gval[b]  = __uint_as_float((unsigned)(vg >> 32));
    }
}

// ---------------- kernel 1: compact dense weight rows (tf32 rounded) -------
__global__ void wcompact_kernel(const float* __restrict__ Phi_w) {
    int t = blockIdx.x * blockDim.x + threadIdx.x;   // one float4 each
    int k  = t >> 9;          // / (NOUT/4)
    int c4 = t & 511;         // % (NOUT/4)
    const float4* src = (const float4*)Phi_w;
    float4 v = src[(size_t)(3 * k) * (NOUT / 4) + c4];
    v.x = tf32r(v.x); v.y = tf32r(v.y); v.z = tf32r(v.z); v.w = tf32r(v.w);
    ((float4*)d_Wd)[(size_t)k * (NOUT / 4) + c4] = v;
}

// ---------------- kernel 2: tf32 tensor-core GEMM + epilogue ---------------
#define BM 128
#define BN 128
#define BK 16
#define ASTRIDE 20
#define BSTRIDE 136

__device__ __forceinline__ void mma_tf32(float* c, const uint32_t* a, const uint32_t* b) {
    asm volatile(
        "mma.sync.aligned.m16n8k8.row.col.f32.tf32.tf32.f32 "
        "{%0,%1,%2,%3}, {%4,%5,%6,%7}, {%8,%9}, {%0,%1,%2,%3};\n"
        : "+f"(c[0]), "+f"(c[1]), "+f"(c[2]), "+f"(c[3])
        : "r"(a[0]), "r"(a[1]), "r"(a[2]), "r"(a[3]), "r"(b[0]), "r"(b[1]));
}

__device__ __forceinline__ void cpa16(float* smemDst, const float4* gmemSrc) {
    uint32_t s = (uint32_t)__cvta_generic_to_shared(smemDst);
    asm volatile("cp.async.cg.shared.global [%0], [%1], 16;\n" :: "r"(s), "l"(gmemSrc));
}

__global__ __launch_bounds__(256, 2) void gemm_kernel(
    const float* __restrict__ Phi_w, const float* __restrict__ Phi_b)
{
    __shared__ float As[2][BM * ASTRIDE];
    __shared__ float Bs[2][BK * BSTRIDE];

    const int tid  = threadIdx.x;
    const int warp = tid >> 5;
    const int lane = tid & 31;
    const int wm   = warp >> 2;
    const int wn   = warp & 3;
    const int bm   = blockIdx.y * BM;
    const int bn   = blockIdx.x * BN;

    const int a_row0 = tid >> 2, a_c40 = tid & 3;
    const int a_row1 = (tid + 256) >> 2, a_c41 = (tid + 256) & 3;
    const int b_row0 = tid >> 5, b_c40 = tid & 31;
    const int b_row1 = (tid + 256) >> 5, b_c41 = (tid + 256) & 31;

    const float4* Ap = (const float4*)d_walls;
    const float4* Bp = (const float4*)d_Wd;

    float acc[4][4][4];
    #pragma unroll
    for (int i = 0; i < 4; i++)
        #pragma unroll
        for (int j = 0; j < 4; j++)
            #pragma unroll
            for (int k = 0; k < 4; k++) acc[i][j][k] = 0.f;

#define LOAD_STAGE(KT, BUF)                                                              \
    do {                                                                                 \
        const int ko4 = (KT) * (BK / 4);                                                 \
        cpa16(&As[BUF][a_row0 * ASTRIDE + a_c40 * 4],                                    \
              &Ap[(size_t)(bm + a_row0) * (S / 4) + ko4 + a_c40]);                       \
        cpa16(&As[BUF][a_row1 * ASTRIDE + a_c41 * 4],                                    \
              &Ap[(size_t)(bm + a_row1) * (S / 4) + ko4 + a_c41]);                       \
        cpa16(&Bs[BUF][b_row0 * BSTRIDE + b_c40 * 4],                                    \
              &Bp[(size_t)((KT) * BK + b_row0) * (NOUT / 4) + (bn >> 2) + b_c40]);       \
        cpa16(&Bs[BUF][b_row1 * BSTRIDE + b_c41 * 4],                                    \
              &Bp[(size_t)((KT) * BK + b_row1) * (NOUT / 4) + (bn >> 2) + b_c41]);       \
        asm volatile("cp.async.commit_group;\n");                                        \
    } while (0)

    LOAD_STAGE(0, 0);

    const int NKT = S / BK;   // 64
    #pragma unroll 1
    for (int kt = 0; kt < NKT; kt++) {
        const int cur = kt & 1;
        if (kt + 1 < NKT) {
            LOAD_STAGE(kt + 1, cur ^ 1);
            asm volatile("cp.async.wait_group 1;\n");
        } else {
            asm volatile("cp.async.wait_group 0;\n");
        }
        __syncthreads();

        #pragma unroll
        for (int kk = 0; kk < BK; kk += 8) {
            uint32_t afr[4][4];
            uint32_t bfr[4][2];
            #pragma unroll
            for (int mt = 0; mt < 4; mt++) {
                const float* p = &As[cur][(wm * 64 + mt * 16 + (lane >> 2)) * ASTRIDE
                                          + kk + (lane & 3)];
                afr[mt][0] = __float_as_uint(p[0]);
                afr[mt][1] = __float_as_uint(p[8 * ASTRIDE]);
                afr[mt][2] = __float_as_uint(p[4]);
                afr[mt][3] = __float_as_uint(p[8 * ASTRIDE + 4]);
            }
            #pragma unroll
            for (int nt = 0; nt < 4; nt++) {
                const float* q = &Bs[cur][(kk + (lane & 3)) * BSTRIDE
                                          + wn * 32 + nt * 8 + (lane >> 2)];
                bfr[nt][0] = __float_as_uint(q[0]);
                bfr[nt][1] = __float_as_uint(q[4 * BSTRIDE]);
            }
            #pragma unroll
            for (int mt = 0; mt < 4; mt++)
                #pragma unroll
                for (int nt = 0; nt < 4; nt++)
                    mma_tf32(acc[mt][nt], afr[mt], bfr[nt]);
        }
        __syncthreads();
    }
#undef LOAD_STAGE

    // ---- epilogue: + agent/goal row gathers + bias, sigmoid, store (r,p) --
    #pragma unroll
    for (int mt = 0; mt < 4; mt++) {
        #pragma unroll
        for (int rsub = 0; rsub < 2; rsub++) {
            const int gr = bm + wm * 64 + mt * 16 + (lane >> 2) + rsub * 8;
            const int ai = d_agent[gr];
            const int gi = d_goal[gr];
            const float av = d_aval[gr];
            const float gv = d_gval[gr];
            const float* arow = Phi_w + (size_t)(3 * ai + 1) * NOUT;
            const float* grow = Phi_w + (size_t)(3 * gi + 2) * NOUT;
            #pragma unroll
            for (int nt = 0; nt < 4; nt++) {
                const int gn = bn + wn * 32 + nt * 8 + (lane & 3) * 2;
                float x0 = acc[mt][nt][rsub * 2 + 0]
                         + av * arow[gn] + gv * grow[gn] + Phi_b[gn];
                float x1 = acc[mt][nt][rsub * 2 + 1]
                         + av * arow[gn + 1] + gv * grow[gn + 1] + Phi_b[gn + 1];
                float2 o;
                o.x = 1.f / (1.f + __expf(-x0));
                o.y = 1.f / (1.f + __expf(-x1));
                *((float2*)&d_phi[(size_t)gr * NOUT + gn]) = o;
            }
        }
    }
}

// -------- kernel 3: warp-per-sample vprop (registers + shfl) + MLP head ----
__global__ __launch_bounds__(256) void vprop_warp_kernel(
    const float* __restrict__ obs,
    const float* __restrict__ L1w, const float* __restrict__ L1b,
    const float* __restrict__ L2w, const float* __restrict__ L2b,
    float* __restrict__ out)
{
    const int warp = threadIdx.x >> 5;
    const int lane = threadIdx.x & 31;
    const int b = blockIdx.x * 8 + warp;
    const int j = lane;                      // column owned by this lane
    const unsigned FULL = 0xFFFFFFFFu;

    __shared__ float ssel[8][36];
    __shared__ float shh[8][16];

    float V[32], r[32], p[32];
    const float2* phi = (const float2*)(d_phi + (size_t)b * NOUT);
    #pragma unroll
    for (int i = 0; i < 32; i++) {
        float2 rp = phi[i * 32 + j];
        r[i] = rp.x; p[i] = rp.y; V[i] = rp.x;
    }

    // 20 Jacobi iterations. prev holds the OLD value of row i-1.
    #pragma unroll 1
    for (int it = 0; it < KITER; it++) {
        float prev = 0.f;
        #pragma unroll
        for (int i = 0; i < 32; i++) {
            float cur = V[i];
            float dn  = (i < 31) ? V[i + 1] : 0.f;     // still old
            float lf  = __shfl_up_sync(FULL, cur, 1);
            float rt  = __shfl_down_sync(FULL, cur, 1);
            if (j == 0)  lf = 0.f;
            if (j == 31) rt = 0.f;
            float nbr = fmaxf(fmaxf(prev, dn), fmaxf(lf, rt));
            V[i] = fmaxf(cur, fmaf(p[i], nbr - r[i], r[i]));
            prev = cur;
        }
    }

    // ---- head: 3x3 gather around agent + 36->16->4 MLP --------------------
    const int ai = d_agent[b];
    const int gi = d_goal[b];
    const int pi = ai >> 5, pj = ai & 31;

    // select rows pi-1, pi, pi+1 of this lane's column into v3 (static loop)
    float v3[3];
    v3[0] = 0.f; v3[1] = 0.f; v3[2] = 0.f;
    #pragma unroll
    for (int i = 0; i < 32; i++) {
        v3[0] = (i == pi - 1) ? V[i] : v3[0];
        v3[1] = (i == pi)     ? V[i] : v3[1];
        v3[2] = (i == pi + 1) ? V[i] : v3[2];
    }

    // lanes 0..8 produce the 9 neighborhood cells; all lanes join the shfls
    const int di = lane / 3, dj = lane - di * 3;     // valid for lane<9
    const int ii = pi + di - 1;
    const int jj = pj + dj - 1;
    int src = jj < 0 ? 0 : (jj > 31 ? 31 : jj);
    float rv0 = __shfl_sync(FULL, v3[0], src);
    float rv1 = __shfl_sync(FULL, v3[1], src);
    float rv2 = __shfl_sync(FULL, v3[2], src);

    if (lane < 9) {
        float vv = (di == 0) ? rv0 : ((di == 1) ? rv1 : rv2);
        bool inb = (ii >= 0) && (ii < 32) && (jj >= 0) && (jj < 32);
        int  sp  = ii * 32 + jj;
        float c0 = inb ? obs[(size_t)b * DIN + sp * 3 + 0] : 0.f;
        float c1 = (lane == 4) ? 1.f : 0.f;          // agent one-hot: center only
        float c2 = (inb && sp == gi) ? 1.f : 0.f;    // goal one-hot
        float c3 = inb ? vv : 0.f;
        ssel[warp][lane * 4 + 0] = c0;
        ssel[warp][lane * 4 + 1] = c1;
        ssel[warp][lane * 4 + 2] = c2;
        ssel[warp][lane * 4 + 3] = c3;
    }
    __syncwarp();
    if (lane < 16) {
        float h = L1b[lane];
        #pragma unroll
        for (int f = 0; f < 36; f++) h = fmaf(ssel[warp][f], L1w[f * 16 + lane], h);
        shh[warp][lane] = fmaxf(h, 0.f);
    }
    __syncwarp();
    if (lane < 4) {
        float o = L2b[lane];
        #pragma unroll
        for (int k = 0; k < 16; k++) o = fmaf(shh[warp][k], L2w[k * 4 + lane], o);
        out[(size_t)b * 4 + lane] = o;
    }
}

// ---------------------------------------------------------------------------
extern "C" void kernel_launch(void* const* d_in, const int* in_sizes, int n_in,
                              void* d_out, int out_size) {
    const float* obs   = (const float*)d_in[0];
    const float* Phi_w = (const float*)d_in[1];
    const float* Phi_b = (const float*)d_in[2];
    const float* L1w   = (const float*)d_in[3];
    const float* L1b   = (const float*)d_in[4];
    const float* L2w   = (const float*)d_in[5];
    const float* L2b   = (const float*)d_in[6];
    float* out = (float*)d_out;

    prep_kernel<<<Bn, 256>>>(obs);
    wcompact_kernel<<<(S * NOUT / 4) / 256, 256>>>(Phi_w);
    dim3 g(NOUT / BN, Bn / BM);
    gemm_kernel<<<g, 256>>>(Phi_w, Phi_b);
    vprop_warp_kernel<<<Bn / 8, 256>>>(obs, L1w, L1b, L2w, L2b, out);
}

// round 5
// speedup vs baseline: 1.9078x; 1.4124x over previous
#include <cuda_runtime.h>
#include <cuda_fp16.h>
#include <cstdint>

#define Bn   4096
#define S    1024     // H*W
#define DIN  3072     // H*W*3
#define NOUT 2048     // 2*H*W
#define KITER 20

// ---------------- scratch (device globals; no allocation allowed) ----------
__device__ __half d_walls[Bn * S];      // fp16 walls, (B,1024)
__device__ __half d_WdT[NOUT * S];      // B^T: [N=2048][K=1024] K-major, fp16
__device__ float  d_phi[Bn * NOUT];     // sigmoid output, interleaved (r,p)
__device__ int    d_agent[Bn];
__device__ int    d_goal[Bn];
__device__ float  d_aval[Bn];
__device__ float  d_gval[Bn];

// ---------------- kernel 0: compact walls + argmax of agent/goal channels --
__global__ void prep_kernel(const float* __restrict__ obs) {
    int b = blockIdx.x;
    const float* row = obs + (size_t)b * DIN;
    __shared__ unsigned long long ka, kg;
    if (threadIdx.x == 0) { ka = 0ull; kg = 0ull; }
    __syncthreads();
    unsigned long long la = 0ull, lg = 0ull;
    for (int s = threadIdx.x; s < S; s += blockDim.x) {
        float w = row[3 * s + 0];
        float a = row[3 * s + 1];
        float g = row[3 * s + 2];
        d_walls[(size_t)b * S + s] = __float2half_rn(w);
        unsigned long long keya =
            ((unsigned long long)__float_as_uint(a) << 32) | (unsigned)(0xFFFFFFFFu - s);
        unsigned long long keyg =
            ((unsigned long long)__float_as_uint(g) << 32) | (unsigned)(0xFFFFFFFFu - s);
        if (keya > la) la = keya;
        if (keyg > lg) lg = keyg;
    }
    atomicMax(&ka, la);
    atomicMax(&kg, lg);
    __syncthreads();
    if (threadIdx.x == 0) {
        unsigned long long va = ka, vg = kg;
        d_agent[b] = (int)(0xFFFFFFFFu - (unsigned)(va & 0xFFFFFFFFull));
        d_aval[b]  = __uint_as_float((unsigned)(va >> 32));
        d_goal[b]  = (int)(0xFFFFFFFFu - (unsigned)(vg & 0xFFFFFFFFull));
        d_gval[b]  = __uint_as_float((unsigned)(vg >> 32));
    }
}

// -------- kernel 1: transpose dense weight rows -> d_WdT[n][k] (fp16) ------
__global__ void wtrans_kernel(const float* __restrict__ Phi_w) {
    __shared__ float t[32][33];
    const int k0 = blockIdx.x * 32, n0 = blockIdx.y * 32;
    const int tx = threadIdx.x & 31, ty = threadIdx.x >> 5;   // 256 thr: ty 0..7
    #pragma unroll
    for (int i = ty; i < 32; i += 8)
        t[i][tx] = Phi_w[(size_t)(3 * (k0 + i)) * NOUT + n0 + tx];
    __syncthreads();
    #pragma unroll
    for (int i = ty; i < 32; i += 8)
        d_WdT[(size_t)(n0 + i) * S + k0 + tx] = __float2half_rn(t[tx][i]);
}

// ---------------- kernel 2: fp16 tensor-core GEMM + epilogue ---------------
#define BM 128
#define BN 128
#define BK 32
#define TSTRIDE 40   // halves per smem row = 80 bytes: 16B-aligned, conflict-free

__device__ __forceinline__ void mma_f16(float* c, const uint32_t* a, const uint32_t* b) {
    asm volatile(
        "mma.sync.aligned.m16n8k16.row.col.f32.f16.f16.f32 "
        "{%0,%1,%2,%3}, {%4,%5,%6,%7}, {%8,%9}, {%0,%1,%2,%3};\n"
        : "+f"(c[0]), "+f"(c[1]), "+f"(c[2]), "+f"(c[3])
        : "r"(a[0]), "r"(a[1]), "r"(a[2]), "r"(a[3]), "r"(b[0]), "r"(b[1]));
}

__device__ __forceinline__ void cpa16(uint32_t smemDst, const void* gmemSrc) {
    asm volatile("cp.async.cg.shared.global [%0], [%1], 16;\n"
                 :: "r"(smemDst), "l"(gmemSrc));
}

__global__ __launch_bounds__(256, 2) void gemm_kernel(
    const float* __restrict__ Phi_w, const float* __restrict__ Phi_b)
{
    __shared__ __align__(16) __half As[2][BM * TSTRIDE];
    __shared__ __align__(16) __half Bs[2][BN * TSTRIDE];

    const int tid  = threadIdx.x;
    const int warp = tid >> 5;
    const int lane = tid & 31;
    const int wm   = warp >> 2;   // 0..1 -> 64 rows
    const int wn   = warp & 3;    // 0..3 -> 32 cols
    const int bm   = blockIdx.y * BM;
    const int bn   = blockIdx.x * BN;

    const uint4* Ap = (const uint4*)d_walls;   // 8 halves per uint4; row = 128 uint4
    const uint4* Bp = (const uint4*)d_WdT;

    const uint32_t sA0 = (uint32_t)__cvta_generic_to_shared(&As[0][0]);
    const uint32_t sA1 = (uint32_t)__cvta_generic_to_shared(&As[1][0]);
    const uint32_t sB0 = (uint32_t)__cvta_generic_to_shared(&Bs[0][0]);
    const uint32_t sB1 = (uint32_t)__cvta_generic_to_shared(&Bs[1][0]);

    float acc[4][4][4];
    #pragma unroll
    for (int i = 0; i < 4; i++)
        #pragma unroll
        for (int j = 0; j < 4; j++)
            #pragma unroll
            for (int k = 0; k < 4; k++) acc[i][j][k] = 0.f;

    // each thread loads 2 A chunks + 2 B chunks of 16B per stage
#define LOAD_STAGE(KT, SA, SB)                                                    \
    do {                                                                          \
        const int ko = (KT) * (BK / 8);                                           \
        _Pragma("unroll")                                                         \
        for (int i = 0; i < 2; i++) {                                             \
            int o = tid + i * 256;                                                \
            int row = o >> 2, c = o & 3;                                          \
            uint32_t dst = (uint32_t)(row * (TSTRIDE * 2) + c * 16);              \
            cpa16((SA) + dst, Ap + (size_t)(bm + row) * (S / 8) + ko + c);        \
            cpa16((SB) + dst, Bp + (size_t)(bn + row) * (S / 8) + ko + c);        \
        }                                                                         \
        asm volatile("cp.async.commit_group;\n");                                 \
    } while (0)

    LOAD_STAGE(0, sA0, sB0);

    const int NKT = S / BK;   // 32
    #pragma unroll 1
    for (int kt = 0; kt < NKT; kt++) {
        const int cur = kt & 1;
        if (kt + 1 < NKT) {
            if (cur) LOAD_STAGE(kt + 1, sA0, sB0);
            else     LOAD_STAGE(kt + 1, sA1, sB1);
            asm volatile("cp.async.wait_group 1;\n");
        } else {
            asm volatile("cp.async.wait_group 0;\n");
        }
        __syncthreads();

        #pragma unroll
        for (int kk = 0; kk < BK; kk += 16) {
            uint32_t afr[4][4];
            uint32_t bfr[4][2];
            const int kh = kk + (lane & 3) * 2;     // half index within row
            #pragma unroll
            for (int mt = 0; mt < 4; mt++) {
                const __half* p = &As[cur][(wm * 64 + mt * 16 + (lane >> 2)) * TSTRIDE + kh];
                afr[mt][0] = *(const uint32_t*)(p);
                afr[mt][1] = *(const uint32_t*)(p + 8 * TSTRIDE);
                afr[mt][2] = *(const uint32_t*)(p + 8);
                afr[mt][3] = *(const uint32_t*)(p + 8 * TSTRIDE + 8);
            }
            #pragma unroll
            for (int nt = 0; nt < 4; nt++) {
                const __half* q = &Bs[cur][(wn * 32 + nt * 8 + (lane >> 2)) * TSTRIDE + kh];
                bfr[nt][0] = *(const uint32_t*)(q);
                bfr[nt][1] = *(const uint32_t*)(q + 8);
            }
            #pragma unroll
            for (int mt = 0; mt < 4; mt++)
                #pragma unroll
                for (int nt = 0; nt < 4; nt++)
                    mma_f16(acc[mt][nt], afr[mt], bfr[nt]);
        }
        __syncthreads();
    }
#undef LOAD_STAGE

    // ---- epilogue: + agent/goal row gathers + bias, sigmoid, store (r,p) --
    #pragma unroll
    for (int mt = 0; mt < 4; mt++) {
        #pragma unroll
        for (int rsub = 0; rsub < 2; rsub++) {
            const int gr = bm + wm * 64 + mt * 16 + (lane >> 2) + rsub * 8;
            const int ai = d_agent[gr];
            const int gi = d_goal[gr];
            const float av = d_aval[gr];
            const float gv = d_gval[gr];
            const float* arow = Phi_w + (size_t)(3 * ai + 1) * NOUT;
            const float* grow = Phi_w + (size_t)(3 * gi + 2) * NOUT;
            #pragma unroll
            for (int nt = 0; nt < 4; nt++) {
                const int gn = bn + wn * 32 + nt * 8 + (lane & 3) * 2;
                float x0 = acc[mt][nt][rsub * 2 + 0]
                         + av * arow[gn] + gv * grow[gn] + Phi_b[gn];
                float x1 = acc[mt][nt][rsub * 2 + 1]
                         + av * arow[gn + 1] + gv * grow[gn + 1] + Phi_b[gn + 1];
                float2 o;
                o.x = 1.f / (1.f + __expf(-x0));
                o.y = 1.f / (1.f + __expf(-x1));
                *((float2*)&d_phi[(size_t)gr * NOUT + gn]) = o;
            }
        }
    }
}

// -------- kernel 3: warp-per-sample vprop (registers + shfl) + MLP head ----
__global__ __launch_bounds__(128) void vprop_warp_kernel(
    const float* __restrict__ obs,
    const float* __restrict__ L1w, const float* __restrict__ L1b,
    const float* __restrict__ L2w, const float* __restrict__ L2b,
    float* __restrict__ out)
{
    const int warp = threadIdx.x >> 5;
    const int lane = threadIdx.x & 31;
    const int b = blockIdx.x * 4 + warp;
    const unsigned FULL = 0xFFFFFFFFu;

    __shared__ float ssel[4][36];
    __shared__ float shh[4][16];

    float V[32], a[32], p[32];
    const float2* phi = (const float2*)(d_phi + (size_t)b * NOUT);
    #pragma unroll
    for (int i = 0; i < 32; i++) {
        float2 rp = phi[i * 32 + lane];
        p[i] = rp.y;
        a[i] = rp.x * (1.f - rp.y);      // r*(1-p)
        V[i] = rp.x;
    }

    // 20 Jacobi iterations; self-inclusion at boundaries is a no-op (V>=r, p<1)
    #pragma unroll 1
    for (int it = 0; it < KITER; it++) {
        float prev = V[0];
        #pragma unroll
        for (int i = 0; i < 32; i++) {
            float cur = V[i];
            float dn  = (i < 31) ? V[i + 1] : cur;
            float lf  = __shfl_up_sync(FULL, cur, 1);    // lane0 -> self
            float rt  = __shfl_down_sync(FULL, cur, 1);  // lane31 -> self
            float nbr = fmaxf(fmaxf(prev, dn), fmaxf(lf, rt));
            V[i] = fmaxf(cur, fmaf(p[i], nbr, a[i]));
            prev = cur;
        }
    }

    // ---- head: 3x3 gather around agent + 36->16->4 MLP --------------------
    const int ai = d_agent[b];
    const int gi = d_goal[b];
    const int pi = ai >> 5, pj = ai & 31;

    float v3[3];
    v3[0] = 0.f; v3[1] = 0.f; v3[2] = 0.f;
    #pragma unroll
    for (int i = 0; i < 32; i++) {
        v3[0] = (i == pi - 1) ? V[i] : v3[0];
        v3[1] = (i == pi)     ? V[i] : v3[1];
        v3[2] = (i == pi + 1) ? V[i] : v3[2];
    }

    const int di = lane / 3, dj = lane - di * 3;     // valid for lane<9
    const int ii = pi + di - 1;
    const int jj = pj + dj - 1;
    int src = jj < 0 ? 0 : (jj > 31 ? 31 : jj);
    float rv0 = __shfl_sync(FULL, v3[0], src);
    float rv1 = __shfl_sync(FULL, v3[1], src);
    float rv2 = __shfl_sync(FULL, v3[2], src);

    if (lane < 9) {
        float vv = (di == 0) ? rv0 : ((di == 1) ? rv1 : rv2);
        bool inb = (ii >= 0) && (ii < 32) && (jj >= 0) && (jj < 32);
        int  sp  = ii * 32 + jj;
        float c0 = inb ? obs[(size_t)b * DIN + sp * 3 + 0] : 0.f;
        float c1 = (lane == 4) ? 1.f : 0.f;          // agent one-hot: center only
        float c2 = (inb && sp == gi) ? 1.f : 0.f;    // goal one-hot
        float c3 = inb ? vv : 0.f;
        ssel[warp][lane * 4 + 0] = c0;
        ssel[warp][lane * 4 + 1] = c1;
        ssel[warp][lane * 4 + 2] = c2;
        ssel[warp][lane * 4 + 3] = c3;
    }
    __syncwarp();
    if (lane < 16) {
        float h = L1b[lane];
        #pragma unroll
        for (int f = 0; f < 36; f++) h = fmaf(ssel[warp][f], L1w[f * 16 + lane], h);
        shh[warp][lane] = fmaxf(h, 0.f);
    }
    __syncwarp();
    if (lane < 4) {
        float o = L2b[lane];
        #pragma unroll
        for (int k = 0; k < 16; k++) o = fmaf(shh[warp][k], L2w[k * 4 + lane], o);
        out[(size_t)b * 4 + lane] = o;
    }
}

// ---------------------------------------------------------------------------
extern "C" void kernel_launch(void* const* d_in, const int* in_sizes, int n_in,
                              void* d_out, int out_size) {
    const float* obs   = (const float*)d_in[0];
    const float* Phi_w = (const float*)d_in[1];
    const float* Phi_b = (const float*)d_in[2];
    const float* L1w   = (const float*)d_in[3];
    const float* L1b   = (const float*)d_in[4];
    const float* L2w   = (const float*)d_in[5];
    const float* L2b   = (const float*)d_in[6];
    float* out = (float*)d_out;

    prep_kernel<<<Bn, 256>>>(obs);
    wtrans_kernel<<<dim3(32, 64), 256>>>(Phi_w);
    dim3 g(NOUT / BN, Bn / BM);
    gemm_kernel<<<g, 256>>>(Phi_w, Phi_b);
    vprop_warp_kernel<<<Bn / 4, 128>>>(obs, L1w, L1b, L2w, L2b, out);
}

// round 6
// speedup vs baseline: 2.1914x; 1.1487x over previous
#include <cuda_runtime.h>
#include <cuda_fp16.h>
#include <cstdint>

#define Bn   4096
#define S    1024     // H*W
#define DIN  3072     // H*W*3
#define NOUT 2048     // 2*H*W
#define KITER 20

// ---------------- scratch (device globals; no allocation allowed) ----------
// A and B packed as 8KB tiles: tile = 128 rows x 32 halves, row stride 64B,
// 16B chunk swizzle: c16' = c16 ^ ((row>>1)&3)  -> ldmatrix conflict-free.
__device__ __half d_pA[Bn * S];         // (Bn/128)*(S/32) tiles
__device__ __half d_pB[NOUT * S];       // (NOUT/128)*(S/32) tiles
__device__ float  d_phi[Bn * NOUT];     // sigmoid output, interleaved (r,p)
__device__ int    d_agent[Bn];
__device__ int    d_goal[Bn];
__device__ float  d_aval[Bn];
__device__ float  d_gval[Bn];

__device__ __forceinline__ int packed_off(int row, int k) {   // row 0..127, k 0..31
    int c16 = ((k >> 3) ^ ((row >> 1) & 3));
    return row * 32 + c16 * 8 + (k & 7);
}

// ---------------- kernel 0: pack walls + argmax of agent/goal channels -----
__global__ void prep_kernel(const float* __restrict__ obs) {
    int b = blockIdx.x;
    const float* row = obs + (size_t)b * DIN;
    __shared__ unsigned long long ka, kg;
    if (threadIdx.x == 0) { ka = 0ull; kg = 0ull; }
    __syncthreads();
    unsigned long long la = 0ull, lg = 0ull;
    __half* tbase = d_pA + (size_t)((b >> 7) * 32) * 4096;
    const int prow = b & 127;
    for (int s = threadIdx.x; s < S; s += blockDim.x) {
        float w = row[3 * s + 0];
        float a = row[3 * s + 1];
        float g = row[3 * s + 2];
        tbase[(size_t)(s >> 5) * 4096 + packed_off(prow, s & 31)] = __float2half_rn(w);
        unsigned long long keya =
            ((unsigned long long)__float_as_uint(a) << 32) | (unsigned)(0xFFFFFFFFu - s);
        unsigned long long keyg =
            ((unsigned long long)__float_as_uint(g) << 32) | (unsigned)(0xFFFFFFFFu - s);
        if (keya > la) la = keya;
        if (keyg > lg) lg = keyg;
    }
    atomicMax(&ka, la);
    atomicMax(&kg, lg);
    __syncthreads();
    if (threadIdx.x == 0) {
        unsigned long long va = ka, vg = kg;
        d_agent[b] = (int)(0xFFFFFFFFu - (unsigned)(va & 0xFFFFFFFFull));
        d_aval[b]  = __uint_as_float((unsigned)(va >> 32));
        d_goal[b]  = (int)(0xFFFFFFFFu - (unsigned)(vg & 0xFFFFFFFFull));
        d_gval[b]  = __uint_as_float((unsigned)(vg >> 32));
    }
}

// ------ kernel 1: transpose dense weight rows -> packed B tiles (fp16) -----
__global__ void wtrans_kernel(const float* __restrict__ Phi_w) {
    __shared__ float t[32][33];
    const int k0 = blockIdx.x * 32, n0 = blockIdx.y * 32;
    const int tx = threadIdx.x & 31, ty = threadIdx.x >> 5;   // 256 thr: ty 0..7
    #pragma unroll
    for (int i = ty; i < 32; i += 8)
        t[i][tx] = Phi_w[(size_t)(3 * (k0 + i)) * NOUT + n0 + tx];
    __syncthreads();
    #pragma unroll
    for (int i = ty; i < 32; i += 8) {
        int n = n0 + i, k = k0 + tx;
        d_pB[(size_t)((n >> 7) * 32 + (k >> 5)) * 4096 + packed_off(n & 127, k & 31)]
            = __float2half_rn(t[tx][i]);
    }
}

// ---------------- kernel 2: fp16 GEMM, bulk-copy pipeline + ldmatrix -------
#define BM 128
#define BN 128
#define NSTG 32
#define TILE_BYTES 16384        // A 8KB + B 8KB per stage
#define SMEM_BUFS 4
#define GEMM_SMEM (1024 + SMEM_BUFS * TILE_BYTES)

__device__ __forceinline__ void mma_f16(float* c, const uint32_t* a, const uint32_t* b) {
    asm volatile(
        "mma.sync.aligned.m16n8k16.row.col.f32.f16.f16.f32 "
        "{%0,%1,%2,%3}, {%4,%5,%6,%7}, {%8,%9}, {%0,%1,%2,%3};\n"
        : "+f"(c[0]), "+f"(c[1]), "+f"(c[2]), "+f"(c[3])
        : "r"(a[0]), "r"(a[1]), "r"(a[2]), "r"(a[3]), "r"(b[0]), "r"(b[1]));
}

__device__ __forceinline__ void ldsm4(uint32_t& r0, uint32_t& r1, uint32_t& r2,
                                      uint32_t& r3, uint32_t addr) {
    asm volatile("ldmatrix.sync.aligned.m8n8.x4.shared.b16 {%0,%1,%2,%3}, [%4];"
                 : "=r"(r0), "=r"(r1), "=r"(r2), "=r"(r3) : "r"(addr));
}

__device__ __forceinline__ void mbar_wait(uint32_t mbar, uint32_t parity) {
    uint32_t done;
    asm volatile(
        "{\n .reg .pred p;\n"
        " mbarrier.try_wait.parity.acquire.cta.shared::cta.b64 p, [%1], %2;\n"
        " selp.b32 %0, 1, 0, p;\n}"
        : "=r"(done) : "r"(mbar), "r"(parity) : "memory");
    if (!done) {
        asm volatile(
            "{\n .reg .pred P1;\n"
            "WL%=:\n"
            " mbarrier.try_wait.parity.acquire.cta.shared::cta.b64 P1, [%0], %1, 0x989680;\n"
            " @P1 bra.uni WD%=;\n"
            " bra.uni WL%=;\n"
            "WD%=:\n}"
            :: "r"(mbar), "r"(parity) : "memory");
    }
}

__device__ __forceinline__ void bulkcp(uint32_t dst, const void* src, uint32_t mbar) {
    asm volatile(
        "cp.async.bulk.shared::cta.global.mbarrier::complete_tx::bytes "
        "[%0], [%1], %2, [%3];"
        :: "r"(dst), "l"(src), "r"(8192u), "r"(mbar) : "memory");
}

__global__ __launch_bounds__(256, 2) void gemm_kernel(
    const float* __restrict__ Phi_w, const float* __restrict__ Phi_b)
{
    extern __shared__ __align__(1024) char smem[];
    const uint32_t sb = (uint32_t)__cvta_generic_to_shared(smem);

    const int tid  = threadIdx.x;
    const int warp = tid >> 5;
    const int lane = tid & 31;
    const int wm   = warp >> 2;   // 0..1 -> 64 rows
    const int wn   = warp & 3;    // 0..3 -> 32 cols
    const int bm   = blockIdx.y * BM;
    const int bn   = blockIdx.x * BN;

    const __half* tA = d_pA + (size_t)(blockIdx.y * 32) * 4096;
    const __half* tB = d_pB + (size_t)(blockIdx.x * 32) * 4096;

    if (tid == 0) {
        #pragma unroll
        for (int i = 0; i < SMEM_BUFS; i++)
            asm volatile("mbarrier.init.shared.b64 [%0], 1;" :: "r"(sb + i * 8) : "memory");
        asm volatile("fence.proxy.async.shared::cta;" ::: "memory");
    }
    __syncthreads();

#define ISSUE(ST)                                                                   \
    do {                                                                            \
        const int _b = (ST) & 3;                                                    \
        const uint32_t _mb = sb + _b * 8;                                           \
        asm volatile("mbarrier.arrive.expect_tx.shared.b64 _, [%0], %1;"            \
                     :: "r"(_mb), "r"((uint32_t)TILE_BYTES) : "memory");            \
        bulkcp(sb + 1024 + _b * TILE_BYTES,        tA + (size_t)(ST) * 4096, _mb);  \
        bulkcp(sb + 1024 + _b * TILE_BYTES + 8192, tB + (size_t)(ST) * 4096, _mb);  \
    } while (0)

    if (tid == 0) { ISSUE(0); ISSUE(1); ISSUE(2); }

    float acc[2][4][4];
    #pragma unroll
    for (int i = 0; i < 2; i++)
        #pragma unroll
        for (int j = 0; j < 4; j++)
            #pragma unroll
            for (int k = 0; k < 4; k++) acc[i * 2][j][k] = 0.f, acc[i * 2 + 1] == 0;
    // (re-init cleanly below)
    float accf[4][4][4];
    #pragma unroll
    for (int i = 0; i < 4; i++)
        #pragma unroll
        for (int j = 0; j < 4; j++)
            #pragma unroll
            for (int k = 0; k < 4; k++) accf[i][j][k] = 0.f;

    #pragma unroll 1
    for (int s = 0; s < NSTG; s++) {
        const int buf = s & 3;
        mbar_wait(sb + buf * 8, (uint32_t)((s >> 2) & 1));

        const uint32_t aBase = sb + 1024 + buf * TILE_BYTES;
        const uint32_t bBase = aBase + 8192;

        #pragma unroll
        for (int kk = 0; kk < 32; kk += 16) {
            uint32_t afr[4][4];
            uint32_t bfr[4][2];
            const int cc = (kk >> 3) + (lane >> 4);     // logical 16B chunk
            #pragma unroll
            for (int mt = 0; mt < 4; mt++) {
                const int row = wm * 64 + mt * 16 + (lane & 15);
                uint32_t addr = aBase + row * 64 + ((cc ^ ((row >> 1) & 3)) << 4);
                ldsm4(afr[mt][0], afr[mt][1], afr[mt][2], afr[mt][3], addr);
            }
            #pragma unroll
            for (int np = 0; np < 2; np++) {
                const int row = wn * 32 + np * 16 + (lane & 15);
                uint32_t addr = bBase + row * 64 + ((cc ^ ((row >> 1) & 3)) << 4);
                ldsm4(bfr[2 * np][0], bfr[2 * np + 1][0],
                      bfr[2 * np][1], bfr[2 * np + 1][1], addr);
            }
            #pragma unroll
            for (int mt = 0; mt < 4; mt++)
                #pragma unroll
                for (int nt = 0; nt < 4; nt++)
                    mma_f16(accf[mt][nt], afr[mt], bfr[nt]);
        }
        __syncthreads();
        if (s + 3 < NSTG && tid == 0) ISSUE(s + 3);
    }
#undef ISSUE

    // ---- epilogue: + agent/goal row gathers + bias, sigmoid, store (r,p) --
    #pragma unroll
    for (int mt = 0; mt < 4; mt++) {
        #pragma unroll
        for (int rsub = 0; rsub < 2; rsub++) {
            const int gr = bm + wm * 64 + mt * 16 + (lane >> 2) + rsub * 8;
            const int ai = d_agent[gr];
            const int gi = d_goal[gr];
            const float av = d_aval[gr];
            const float gv = d_gval[gr];
            const float* arow = Phi_w + (size_t)(3 * ai + 1) * NOUT;
            const float* grow = Phi_w + (size_t)(3 * gi + 2) * NOUT;
            #pragma unroll
            for (int nt = 0; nt < 4; nt++) {
                const int gn = bn + wn * 32 + nt * 8 + (lane & 3) * 2;
                float x0 = accf[mt][nt][rsub * 2 + 0]
                         + av * arow[gn] + gv * grow[gn] + Phi_b[gn];
                float x1 = accf[mt][nt][rsub * 2 + 1]
                         + av * arow[gn + 1] + gv * grow[gn + 1] + Phi_b[gn + 1];
                float2 o;
                o.x = 1.f / (1.f + __expf(-x0));
                o.y = 1.f / (1.f + __expf(-x1));
                *((float2*)&d_phi[(size_t)gr * NOUT + gn]) = o;
            }
        }
    }
}

// -------- kernel 3: warp-per-sample vprop (registers + shfl) + MLP head ----
__global__ __launch_bounds__(128) void vprop_warp_kernel(
    const float* __restrict__ obs,
    const float* __restrict__ L1w, const float* __restrict__ L1b,
    const float* __restrict__ L2w, const float* __restrict__ L2b,
    float* __restrict__ out)
{
    const int warp = threadIdx.x >> 5;
    const int lane = threadIdx.x & 31;
    const int b = blockIdx.x * 4 + warp;
    const unsigned FULL = 0xFFFFFFFFu;

    __shared__ float ssel[4][36];
    __shared__ float shh[4][16];

    float V[32], a[32], p[32];
    const float2* phi = (const float2*)(d_phi + (size_t)b * NOUT);
    #pragma unroll
    for (int i = 0; i < 32; i++) {
        float2 rp = phi[i * 32 + lane];
        p[i] = rp.y;
        a[i] = rp.x * (1.f - rp.y);      // r*(1-p)
        V[i] = rp.x;
    }

    // 20 Jacobi iterations; self-inclusion at boundaries is a no-op (V>=r, p<1)
    #pragma unroll 1
    for (int it = 0; it < KITER; it++) {
        float prev = V[0];
        #pragma unroll
        for (int i = 0; i < 32; i++) {
            float cur = V[i];
            float dn  = (i < 31) ? V[i + 1] : cur;
            float lf  = __shfl_up_sync(FULL, cur, 1);    // lane0 -> self
            float rt  = __shfl_down_sync(FULL, cur, 1);  // lane31 -> self
            float nbr = fmaxf(fmaxf(prev, dn), fmaxf(lf, rt));
            V[i] = fmaxf(cur, fmaf(p[i], nbr, a[i]));
            prev = cur;
        }
    }

    // ---- head: 3x3 gather around agent + 36->16->4 MLP --------------------
    const int ai = d_agent[b];
    const int gi = d_goal[b];
    const int pi = ai >> 5, pj = ai & 31;

    float v3[3];
    v3[0] = 0.f; v3[1] = 0.f; v3[2] = 0.f;
    #pragma unroll
    for (int i = 0; i < 32; i++) {
        v3[0] = (i == pi - 1) ? V[i] : v3[0];
        v3[1] = (i == pi)     ? V[i] : v3[1];
        v3[2] = (i == pi + 1) ? V[i] : v3[2];
    }

    const int di = lane / 3, dj = lane - di * 3;     // valid for lane<9
    const int ii = pi + di - 1;
    const int jj = pj + dj - 1;
    int src = jj < 0 ? 0 : (jj > 31 ? 31 : jj);
    float rv0 = __shfl_sync(FULL, v3[0], src);
    float rv1 = __shfl_sync(FULL, v3[1], src);
    float rv2 = __shfl_sync(FULL, v3[2], src);

    if (lane < 9) {
        float vv = (di == 0) ? rv0 : ((di == 1) ? rv1 : rv2);
        bool inb = (ii >= 0) && (ii < 32) && (jj >= 0) && (jj < 32);
        int  sp  = ii * 32 + jj;
        float c0 = inb ? obs[(size_t)b * DIN + sp * 3 + 0] : 0.f;
        float c1 = (lane == 4) ? 1.f : 0.f;          // agent one-hot: center only
        float c2 = (inb && sp == gi) ? 1.f : 0.f;    // goal one-hot
        float c3 = inb ? vv : 0.f;
        ssel[warp][lane * 4 + 0] = c0;
        ssel[warp][lane * 4 + 1] = c1;
        ssel[warp][lane * 4 + 2] = c2;
        ssel[warp][lane * 4 + 3] = c3;
    }
    __syncwarp();
    if (lane < 16) {
        float h = L1b[lane];
        #pragma unroll
        for (int f = 0; f < 36; f++) h = fmaf(ssel[warp][f], L1w[f * 16 + lane], h);
        shh[warp][lane] = fmaxf(h, 0.f);
    }
    __syncwarp();
    if (lane < 4) {
        float o = L2b[lane];
        #pragma unroll
        for (int k = 0; k < 16; k++) o = fmaf(shh[warp][k], L2w[k * 4 + lane], o);
        out[(size_t)b * 4 + lane] = o;
    }
}

// ---------------------------------------------------------------------------
extern "C" void kernel_launch(void* const* d_in, const int* in_sizes, int n_in,
                              void* d_out, int out_size) {
    const float* obs   = (const float*)d_in[0];
    const float* Phi_w = (const float*)d_in[1];
    const float* Phi_b = (const float*)d_in[2];
    const float* L1w   = (const float*)d_in[3];
    const float* L1b   = (const float*)d_in[4];
    const float* L2w   = (const float*)d_in[5];
    const float* L2b   = (const float*)d_in[6];
    float* out = (float*)d_out;

    prep_kernel<<<Bn, 256>>>(obs);
    wtrans_kernel<<<dim3(32, 64), 256>>>(Phi_w);
    cudaFuncSetAttribute(gemm_kernel,
                         cudaFuncAttributeMaxDynamicSharedMemorySize, GEMM_SMEM);
    dim3 g(NOUT / BN, Bn / BM);
    gemm_kernel<<<g, 256, GEMM_SMEM>>>(Phi_w, Phi_b);
    vprop_warp_kernel<<<Bn / 4, 128>>>(obs, L1w, L1b, L2w, L2b, out);
}